// round 5
// baseline (speedup 1.0000x reference)
#include <cuda_runtime.h>
#include <cuda_bf16.h>

// Fixed shapes: B=64, P=68, H=W=64  ->  4352 tiles of 4096 pixels
#define HW       4096
#define NTHREADS 512
#define NWARPS   (NTHREADS / 32)
#define EPS      1e-5f
#define LOG2E    1.4426950408889634f
#define LN2      0.6931471805599453f

// Raw MUFU intrinsics (exp2f/log2f are PRECISE libm without -use_fast_math)
__device__ __forceinline__ float ex2(float x) {
    float r; asm("ex2.approx.ftz.f32 %0, %1;" : "=f"(r) : "f"(x)); return r;
}
__device__ __forceinline__ float lg2(float x) {
    float r; asm("lg2.approx.f32 %0, %1;" : "=f"(r) : "f"(x)); return r;
}

__global__ __launch_bounds__(NTHREADS)
void gauss_kl_kernel(const float* __restrict__ hm,
                     const float* __restrict__ means,
                     const float* __restrict__ cov,
                     float* __restrict__ out,
                     float inv_rows)
{
    const int bp  = blockIdx.x;
    const int tid = threadIdx.x;

    // Front-batch the 2 streaming LDG.128 loads (consumed only after barrier;
    // latency fully hidden behind pass 1 + reduction)
    const float4* hm4 = reinterpret_cast<const float4*>(hm + (size_t)bp * HW);
    const float4 h0 = __ldcs(&hm4[tid]);
    const float4 h1 = __ldcs(&hm4[tid + NTHREADS]);

    // Per-tile Gaussian parameters (broadcast, L2-hit)
    const float mx  = means[bp * 2 + 0];
    const float my  = means[bp * 2 + 1];
    const float s00 = cov[bp * 4 + 0];
    const float s01 = cov[bp * 4 + 1];
    const float s10 = cov[bp * 4 + 2];
    const float s11 = cov[bp * 4 + 3];
    const float det = fmaf(s00, s11, -s01 * s10) + EPS;
    const float inv_det = LOG2E / det;           // fold log2(e) in
    // lp2 = log2(exp(-quad/2)) = Ac*dx^2 + Bc*dx*dy + Cc*dy^2
    const float Ac = -0.5f * s11 * inv_det;
    const float Bc =  0.5f * (s01 + s10) * inv_det;
    const float Cc = -0.5f * s00 * inv_det;

    // Geometry: i4 = tid + k*512 -> row = (tid>>4) + 32k, x0 = (tid&15)*4
    const float xm  = (float)((tid & 15) << 2) - mx;
    const float dx0 = xm,        dx1 = xm + 1.0f;
    const float dx2 = xm + 2.0f, dx3 = xm + 3.0f;
    const float dyb = (float)(tid >> 4) - my;

    // Pass 1: e = 2^lp2, S = sum e   (8 pixels, all scalar)
    float e[8];
    float S;
    {
        const float dyA   = dyb;
        const float bdyA  = Bc * dyA;
        const float cdy2A = (Cc * dyA) * dyA;
        e[0] = ex2(fmaf(fmaf(Ac, dx0, bdyA), dx0, cdy2A));
        e[1] = ex2(fmaf(fmaf(Ac, dx1, bdyA), dx1, cdy2A));
        e[2] = ex2(fmaf(fmaf(Ac, dx2, bdyA), dx2, cdy2A));
        e[3] = ex2(fmaf(fmaf(Ac, dx3, bdyA), dx3, cdy2A));
        const float dyB   = dyb + 32.0f;
        const float bdyB  = Bc * dyB;
        const float cdy2B = (Cc * dyB) * dyB;
        e[4] = ex2(fmaf(fmaf(Ac, dx0, bdyB), dx0, cdy2B));
        e[5] = ex2(fmaf(fmaf(Ac, dx1, bdyB), dx1, cdy2B));
        e[6] = ex2(fmaf(fmaf(Ac, dx2, bdyB), dx2, cdy2B));
        e[7] = ex2(fmaf(fmaf(Ac, dx3, bdyB), dx3, cdy2B));
        S = ((e[0] + e[1]) + (e[2] + e[3])) + ((e[4] + e[5]) + (e[6] + e[7]));
    }

    // Block reduction of S (16 warps)
    __shared__ float ws[NWARPS];
    __shared__ float s_bcast;
#pragma unroll
    for (int o = 16; o > 0; o >>= 1) S += __shfl_xor_sync(0xffffffffu, S, o);
    const int wid = tid >> 5, lid = tid & 31;
    if (lid == 0) ws[wid] = S;
    __syncthreads();
    if (tid < NWARPS) {
        float v = ws[tid];
#pragma unroll
        for (int o = NWARPS / 2; o > 0; o >>= 1)
            v += __shfl_xor_sync((1u << NWARPS) - 1u, v, o);
        if (tid == 0) s_bcast = v;
    }
    __syncthreads();
    const float Sfull = s_bcast;
    const float c = EPS * Sfull;                 // pr + eps = (e + c)/S

    // Pass 2 (registers only): acc = sum hm * (lg2(hm) - lg2(e + c))
    // (sum hm == 1 per tile by construction; hsum reduction dropped)
    float acc = 0.0f;
    {
        const float hv[8] = { h0.x, h0.y, h0.z, h0.w, h1.x, h1.y, h1.z, h1.w };
#pragma unroll
        for (int j = 0; j < 8; j++) {
            const float d = lg2(hv[j]) - lg2(e[j] + c);
            acc = fmaf(hv[j], d, acc);
        }
    }

    // Block reduction of acc
#pragma unroll
    for (int o = 16; o > 0; o >>= 1) acc += __shfl_xor_sync(0xffffffffu, acc, o);
    if (lid == 0) ws[wid] = acc;
    __syncthreads();
    if (tid < NWARPS) {
        float v = ws[tid];
#pragma unroll
        for (int o = NWARPS / 2; o > 0; o >>= 1)
            v += __shfl_xor_sync((1u << NWARPS) - 1u, v, o);
        if (tid == 0) {
            // loss_tile = ln2 * (acc + lg2(S))   [sum(hm) == 1]
            const float tile = LN2 * (v + lg2(Sfull));
            atomicAdd(out, tile * inv_rows);
        }
    }
}

extern "C" void kernel_launch(void* const* d_in, const int* in_sizes, int n_in,
                              void* d_out, int out_size)
{
    const float* hm    = (const float*)d_in[0];   // [B,P,H,W]
    const float* means = (const float*)d_in[1];   // [B,P,2]
    const float* cov   = (const float*)d_in[2];   // [B,P,4]
    float* out = (float*)d_out;

    const int n_bp = in_sizes[1] / 2;             // 4352

    cudaMemsetAsync(out, 0, (size_t)out_size * sizeof(float));
    gauss_kl_kernel<<<n_bp, NTHREADS>>>(hm, means, cov, out, 1.0f / (float)n_bp);
}

// round 6
// speedup vs baseline: 1.0115x; 1.0115x over previous
#include <cuda_runtime.h>
#include <cuda_bf16.h>

// Fixed shapes: B=64, P=68, H=W=64 -> 4352 tiles of 4096 pixels
#define HW       4096
#define NTHREADS 256
#define GRIDX    592          // 4 persistent blocks per SM (148 SMs)
#define EPS      1e-5f
#define LOG2E    1.4426950408889634f
#define LN2      0.6931471805599453f

__device__ __forceinline__ float ex2(float x) {
    float r; asm("ex2.approx.ftz.f32 %0, %1;" : "=f"(r) : "f"(x)); return r;
}
__device__ __forceinline__ float lg2(float x) {
    float r; asm("lg2.approx.f32 %0, %1;" : "=f"(r) : "f"(x)); return r;
}
__device__ __forceinline__ void cp_async16(void* smem_dst, const void* gmem_src) {
    unsigned s = (unsigned)__cvta_generic_to_shared(smem_dst);
    asm volatile("cp.async.cg.shared.global [%0], [%1], 16;" :: "r"(s), "l"(gmem_src));
}

__global__ __launch_bounds__(NTHREADS)
void gauss_kl_kernel(const float* __restrict__ hm,
                     const float* __restrict__ means,
                     const float* __restrict__ cov,
                     float* __restrict__ out,
                     int n_tiles, float inv_rows)
{
    __shared__ float4 sbuf[2][HW / 4];     // 2 x 16KB ping-pong heatmap buffers
    __shared__ float  ws[2][NTHREADS / 32];

    const int tid = threadIdx.x;
    const int wid = tid >> 5, lid = tid & 31;
    const int stride = GRIDX;
    const int t0 = blockIdx.x;

    // Prologue: stream first tile into buffer 0
    if (t0 < n_tiles) {
        const float4* g = (const float4*)(hm + (size_t)t0 * HW);
#pragma unroll
        for (int k = 0; k < 4; k++)
            cp_async16(&sbuf[0][tid + k * NTHREADS], g + tid + k * NTHREADS);
    }
    asm volatile("cp.async.commit_group;");

    // Geometry constants (k-group: pixel row = (tid>>4) + 16k, x0 = (tid&15)*4)
    const float xg = (float)((tid & 15) << 2);
    const float yg = (float)(tid >> 4);

    float acc = 0.0f;     // sum over pixels: hm*(lg2 hm - lg2(e+c))
    float lsum = 0.0f;    // tid0 only: sum over tiles of lg2(S_t)
    int buf = 0, it = 0;

    for (int t = t0; t < n_tiles; t += stride, buf ^= 1, it ^= 1) {
        // Prefetch next tile into the other buffer (empty commit keeps accounting)
        const int nt = t + stride;
        if (nt < n_tiles) {
            const float4* g = (const float4*)(hm + (size_t)nt * HW);
#pragma unroll
            for (int k = 0; k < 4; k++)
                cp_async16(&sbuf[buf ^ 1][tid + k * NTHREADS], g + tid + k * NTHREADS);
        }
        asm volatile("cp.async.commit_group;");

        // Per-tile Gaussian parameters (broadcast LDG)
        const float mx  = means[t * 2 + 0];
        const float my  = means[t * 2 + 1];
        const float s00 = cov[t * 4 + 0];
        const float s01 = cov[t * 4 + 1];
        const float s10 = cov[t * 4 + 2];
        const float s11 = cov[t * 4 + 3];
        const float det = fmaf(s00, s11, -s01 * s10) + EPS;
        const float inv_det = LOG2E / det;
        const float Ac = -0.5f * s11 * inv_det;
        const float Bc =  0.5f * (s01 + s10) * inv_det;
        const float Cc = -0.5f * s00 * inv_det;

        const float xm  = xg - mx;
        const float dx0 = xm,        dx1 = xm + 1.0f;
        const float dx2 = xm + 2.0f, dx3 = xm + 3.0f;
        const float dyb = yg - my;

        // Pass 1: e = 2^lp2 (MUFU EX2), S = sum e
        float e[16];
        float S = 0.0f;
#pragma unroll
        for (int k = 0; k < 4; k++) {
            const float dy   = dyb + (float)(16 * k);
            const float bdy  = Bc * dy;
            const float cdy2 = (Cc * dy) * dy;
            const float e0 = ex2(fmaf(fmaf(Ac, dx0, bdy), dx0, cdy2));
            const float e1 = ex2(fmaf(fmaf(Ac, dx1, bdy), dx1, cdy2));
            const float e2 = ex2(fmaf(fmaf(Ac, dx2, bdy), dx2, cdy2));
            const float e3 = ex2(fmaf(fmaf(Ac, dx3, bdy), dx3, cdy2));
            e[4*k+0] = e0; e[4*k+1] = e1; e[4*k+2] = e2; e[4*k+3] = e3;
            S += (e0 + e1) + (e2 + e3);
        }

        // Warp-reduce S; lane0 publishes partial
#pragma unroll
        for (int o = 16; o > 0; o >>= 1) S += __shfl_xor_sync(0xffffffffu, S, o);
        if (lid == 0) ws[it][wid] = S;

        // Current tile's heatmap must be resident; ONE barrier publishes
        // both the cp.async data and the S partials.
        asm volatile("cp.async.wait_group 1;");
        __syncthreads();

        const float Sfull = ((ws[it][0] + ws[it][1]) + (ws[it][2] + ws[it][3]))
                          + ((ws[it][4] + ws[it][5]) + (ws[it][6] + ws[it][7]));
        const float c = EPS * Sfull;            // pr + eps = (e + c)/S
        if (tid == 0) lsum += lg2(Sfull);

        // Pass 2: read heatmap from smem (LDS.128), accumulate KL
#pragma unroll
        for (int k = 0; k < 4; k++) {
            const float4 h = sbuf[buf][tid + k * NTHREADS];
            acc = fmaf(h.x, lg2(h.x) - lg2(e[4*k+0] + c), acc);
            acc = fmaf(h.y, lg2(h.y) - lg2(e[4*k+1] + c), acc);
            acc = fmaf(h.z, lg2(h.z) - lg2(e[4*k+2] + c), acc);
            acc = fmaf(h.w, lg2(h.w) - lg2(e[4*k+3] + c), acc);
        }
    }

    // Epilogue: one block-level reduction + one global atomic per block
#pragma unroll
    for (int o = 16; o > 0; o >>= 1) acc += __shfl_xor_sync(0xffffffffu, acc, o);
    __syncthreads();                       // ws reuse safety
    if (lid == 0) ws[0][wid] = acc;
    __syncthreads();
    if (tid == 0) {
        float v = ((ws[0][0] + ws[0][1]) + (ws[0][2] + ws[0][3]))
                + ((ws[0][4] + ws[0][5]) + (ws[0][6] + ws[0][7]));
        // per-tile: ln2 * (acc_tile + lg2(S_tile))  [sum(hm)==1 per tile]
        const float contrib = LN2 * (v + lsum);
        atomicAdd(out, contrib * inv_rows);
    }
}

extern "C" void kernel_launch(void* const* d_in, const int* in_sizes, int n_in,
                              void* d_out, int out_size)
{
    const float* hm    = (const float*)d_in[0];   // [B,P,H,W]
    const float* means = (const float*)d_in[1];   // [B,P,2]
    const float* cov   = (const float*)d_in[2];   // [B,P,4]
    float* out = (float*)d_out;

    const int n_tiles = in_sizes[1] / 2;          // 4352

    cudaMemsetAsync(out, 0, (size_t)out_size * sizeof(float));
    gauss_kl_kernel<<<GRIDX, NTHREADS>>>(hm, means, cov, out, n_tiles,
                                         1.0f / (float)n_tiles);
}

// round 7
// speedup vs baseline: 1.1137x; 1.1011x over previous
#include <cuda_runtime.h>

// Fixed shapes: B=64, P=68, H=W=64 -> 4352 tiles of 4096 pixels
#define HW       4096
#define NTHREADS 256
#define NWARPS   8
#define EPS      1e-5f
#define LOG2E    1.4426950408889634f
#define LN2      0.6931471805599453f

// Raw MUFU intrinsics (exp2f/log2f are PRECISE libm without -use_fast_math)
__device__ __forceinline__ float ex2(float x) {
    float r; asm("ex2.approx.ftz.f32 %0, %1;" : "=f"(r) : "f"(x)); return r;
}
__device__ __forceinline__ float lg2(float x) {
    float r; asm("lg2.approx.f32 %0, %1;" : "=f"(r) : "f"(x)); return r;
}

__global__ __launch_bounds__(NTHREADS)
void gauss_kl_kernel(const float* __restrict__ hm,
                     const float* __restrict__ means,
                     const float* __restrict__ cov,
                     float* __restrict__ out,
                     float inv_rows)
{
    const int bp  = blockIdx.x;
    const int tid = threadIdx.x;

    // Front-batch the 4 streaming LDG.128 loads
    const float4* hm4 = reinterpret_cast<const float4*>(hm + (size_t)bp * HW);
    float4 h[4];
#pragma unroll
    for (int k = 0; k < 4; k++) h[k] = __ldcs(&hm4[tid + k * NTHREADS]);

    // Per-tile Gaussian parameters
    const float mx  = __ldg(&means[bp * 2 + 0]);
    const float my  = __ldg(&means[bp * 2 + 1]);
    const float s00 = __ldg(&cov[bp * 4 + 0]);
    const float s01 = __ldg(&cov[bp * 4 + 1]);
    const float s10 = __ldg(&cov[bp * 4 + 2]);
    const float s11 = __ldg(&cov[bp * 4 + 3]);
    const float det = fmaf(s00, s11, -s01 * s10) + EPS;
    const float inv_det = LOG2E / det;
    // lp2 = log2(exp(-quad/2)) = Ac*dx^2 + Bc*dx*dy + Cc*dy^2
    const float Ac = -0.5f * s11 * inv_det;
    const float Bc =  0.5f * (s01 + s10) * inv_det;
    const float Cc = -0.5f * s00 * inv_det;

    // Geometry: i4 = tid + 256k -> row = (tid>>4) + 16k, x0 = (tid&15)*4
    const float xm  = (float)((tid & 15) << 2) - mx;
    const float dx0 = xm,        dx1 = xm + 1.0f;
    const float dx2 = xm + 2.0f, dx3 = xm + 3.0f;
    const float dyb = (float)(tid >> 4) - my;

    // Pass 1: e = 2^lp2 (EX2), S = pairwise-tree sum of e
    float e[16];
    float S = 0.0f;
#pragma unroll
    for (int k = 0; k < 4; k++) {
        const float dy   = dyb + (float)(16 * k);
        const float bdy  = Bc * dy;
        const float cdy2 = (Cc * dy) * dy;
        const float e0 = ex2(fmaf(fmaf(Ac, dx0, bdy), dx0, cdy2));
        const float e1 = ex2(fmaf(fmaf(Ac, dx1, bdy), dx1, cdy2));
        const float e2 = ex2(fmaf(fmaf(Ac, dx2, bdy), dx2, cdy2));
        const float e3 = ex2(fmaf(fmaf(Ac, dx3, bdy), dx3, cdy2));
        e[4*k+0] = e0; e[4*k+1] = e1; e[4*k+2] = e2; e[4*k+3] = e3;
        S += (e0 + e1) + (e2 + e3);
    }

    // Reduce S: warp shfl, lane0 -> smem, ONE barrier, all threads sum 8 partials
    __shared__ float ws[NWARPS];
    __shared__ float wa[NWARPS];
    const int wid = tid >> 5, lid = tid & 31;
#pragma unroll
    for (int o = 16; o > 0; o >>= 1) S += __shfl_xor_sync(0xffffffffu, S, o);
    if (lid == 0) ws[wid] = S;
    __syncthreads();
    const float Sfull = ((ws[0] + ws[1]) + (ws[2] + ws[3]))
                      + ((ws[4] + ws[5]) + (ws[6] + ws[7]));
    const float c = EPS * Sfull;                 // pr + eps = (e + c)/S

    // Pass 2 (registers only): acc = sum hm * (lg2(hm) - lg2(e + c))
    float acc = 0.0f;
#pragma unroll
    for (int k = 0; k < 4; k++) {
        acc = fmaf(h[k].x, lg2(h[k].x) - lg2(e[4*k+0] + c), acc);
        acc = fmaf(h[k].y, lg2(h[k].y) - lg2(e[4*k+1] + c), acc);
        acc = fmaf(h[k].z, lg2(h[k].z) - lg2(e[4*k+2] + c), acc);
        acc = fmaf(h[k].w, lg2(h[k].w) - lg2(e[4*k+3] + c), acc);
    }

    // Reduce acc: shfl, lane0 -> smem, one barrier, tid0 finishes + atomic
#pragma unroll
    for (int o = 16; o > 0; o >>= 1) acc += __shfl_xor_sync(0xffffffffu, acc, o);
    if (lid == 0) wa[wid] = acc;
    __syncthreads();
    if (tid == 0) {
        const float v = ((wa[0] + wa[1]) + (wa[2] + wa[3]))
                      + ((wa[4] + wa[5]) + (wa[6] + wa[7]));
        // loss_tile = ln2 * (acc + lg2(S))   [sum(hm) == 1 per tile]
        atomicAdd(out, (LN2 * inv_rows) * (v + lg2(Sfull)));
    }
}

extern "C" void kernel_launch(void* const* d_in, const int* in_sizes, int n_in,
                              void* d_out, int out_size)
{
    const float* hm    = (const float*)d_in[0];   // [B,P,H,W]
    const float* means = (const float*)d_in[1];   // [B,P,2]
    const float* cov   = (const float*)d_in[2];   // [B,P,4]
    float* out = (float*)d_out;

    const int n_bp = in_sizes[1] / 2;             // 4352

    cudaMemsetAsync(out, 0, (size_t)out_size * sizeof(float));
    gauss_kl_kernel<<<n_bp, NTHREADS>>>(hm, means, cov, out, 1.0f / (float)n_bp);
}